// round 1
// baseline (speedup 1.0000x reference)
#include <cuda_runtime.h>
#include <math.h>

#define BB 4
#define CIN 64
#define HH 128
#define WWD 128
#define LL 16384
#define DD 128
#define DBL 20
#define NS 8
#define NCH 128
#define CHL 128

// scratch (static __device__ allocations are allowed)
__device__ float g_xin [BB*LL*DD];   // (b,l,d) pre-conv xin; later reused for gated v
__device__ float g_zg  [BB*LL*DD];   // gelu(z), (b,l,d)
__device__ float g_xs  [BB*LL*DD];   // gelu(conv(xin)), (b,l,d)
__device__ float g_xdbl[BB*DBL*LL];  // (b,c,l) pre-1dconv
__device__ float g_delta[BB*LL*DD];  // (b,l,d)
__device__ float g_Bn  [BB*LL*NS];   // (b,l,n)
__device__ float g_Cn  [BB*LL*NS];   // (b,l,n)
__device__ float g_ap  [BB*NCH*DD*NS];
__device__ float g_hs  [BB*NCH*DD*NS];
__device__ float g_hi  [BB*NCH*DD*NS];
__device__ float g_y   [BB*LL*DD];   // (b,l,d)

__device__ __forceinline__ float gelu_exact(float x){
    return 0.5f*x*(1.f + erff(x*0.70710678118654752f));
}
__device__ __forceinline__ float ex2(float x){
    float r; asm("ex2.approx.f32 %0, %1;" : "=f"(r) : "f"(x)); return r;
}
__device__ __forceinline__ float softplusf(float x){
    return x > 20.f ? x : log1pf(__expf(x));
}

// ---------------------------------------------------------------- K1: in_proj
// out[b,l,dd] = sum_c x[b,c,l] * W[dd,c]; dd<128 -> g_xin, dd>=128 -> gelu -> g_zg
__global__ void k1_inproj(const float* __restrict__ x, const float* __restrict__ Wp){
    __shared__ float xs[64][32];
    __shared__ float Wt[32][257];
    int tid = threadIdx.x;
    int b  = blockIdx.x >> 9;
    int l0 = (blockIdx.x & 511) << 5;
    for (int i = tid; i < 2048; i += 256){
        int c = i >> 5, l = i & 31;
        xs[c][l] = x[(b*64 + c)*LL + l0 + l];
    }
    float acc[32];
#pragma unroll
    for (int i = 0; i < 32; i++) acc[i] = 0.f;
#pragma unroll
    for (int half = 0; half < 2; half++){
        __syncthreads();
        {
            int c = tid & 31, dbase = tid >> 5;
#pragma unroll
            for (int k = 0; k < 32; k++){
                int d = dbase + (k << 3);
                Wt[c][d] = Wp[d*64 + half*32 + c];
            }
        }
        __syncthreads();
#pragma unroll 4
        for (int c = 0; c < 32; c++){
            float w = Wt[c][tid];
            const float4* xr = (const float4*)xs[half*32 + c];
#pragma unroll
            for (int l4 = 0; l4 < 8; l4++){
                float4 xv = xr[l4];
                acc[l4*4+0] = fmaf(w, xv.x, acc[l4*4+0]);
                acc[l4*4+1] = fmaf(w, xv.y, acc[l4*4+1]);
                acc[l4*4+2] = fmaf(w, xv.z, acc[l4*4+2]);
                acc[l4*4+3] = fmaf(w, xv.w, acc[l4*4+3]);
            }
        }
    }
    if (tid < 128){
#pragma unroll
        for (int l = 0; l < 32; l++)
            g_xin[(b*LL + l0 + l)*DD + tid] = acc[l];
    } else {
        int d = tid - 128;
#pragma unroll
        for (int l = 0; l < 32; l++)
            g_zg[(b*LL + l0 + l)*DD + d] = gelu_exact(acc[l]);
    }
}

// ------------------------------------------------- K2: depthwise 3x3 conv + gelu
__global__ void k2_conv(const float* __restrict__ cw, const float* __restrict__ cb){
    int idx = blockIdx.x*256 + threadIdx.x;
    int d4 = idx & 31; int p = idx >> 5;
    int w = p & 127; int h = (p >> 7) & 127; int b = p >> 14;
    int d = d4 << 2;
    float a0 = cb[d], a1 = cb[d+1], a2 = cb[d+2], a3 = cb[d+3];
#pragma unroll
    for (int kh = 0; kh < 3; kh++){
        int hh = h + kh - 1;
        if (hh < 0 || hh > 127) continue;
#pragma unroll
        for (int kw = 0; kw < 3; kw++){
            int ww = w + kw - 1;
            if (ww < 0 || ww > 127) continue;
            float4 xv = *(const float4*)&g_xin[(b*LL + hh*128 + ww)*DD + d];
            int ko = kh*3 + kw;
            a0 = fmaf(xv.x, cw[(d+0)*9+ko], a0);
            a1 = fmaf(xv.y, cw[(d+1)*9+ko], a1);
            a2 = fmaf(xv.z, cw[(d+2)*9+ko], a2);
            a3 = fmaf(xv.w, cw[(d+3)*9+ko], a3);
        }
    }
    float4 o;
    o.x = gelu_exact(a0); o.y = gelu_exact(a1);
    o.z = gelu_exact(a2); o.w = gelu_exact(a3);
    *(float4*)&g_xs[(b*LL + h*128 + w)*DD + d] = o;
}

// ---------------------------------------------------------------- K3: x_proj
// g_xdbl[b,c,l] = sum_d g_xs[b,l,d] * xw[c,d]
__global__ void k3_xproj(const float* __restrict__ xw){
    __shared__ float xsm[128][36];   // [d][l], padded, 16B-aligned rows
    __shared__ float wsm[20][128];
    int tid = threadIdx.x;           // blockDim = 160
    int b  = blockIdx.x >> 9;
    int l0 = (blockIdx.x & 511) << 5;
    for (int i = tid; i < 4096; i += 160){
        int l = i >> 7, d = i & 127;
        xsm[d][l] = g_xs[(b*LL + l0 + l)*DD + d];
    }
    for (int i = tid; i < 2560; i += 160) ((float*)wsm)[i] = xw[i];
    __syncthreads();
    int c = tid / 8, lg = tid & 7;
    float4 acc = make_float4(0.f, 0.f, 0.f, 0.f);
    for (int k = 0; k < 128; k++){
        float wv = wsm[c][k];
        float4 v = *(const float4*)&xsm[k][lg*4];
        acc.x = fmaf(wv, v.x, acc.x); acc.y = fmaf(wv, v.y, acc.y);
        acc.z = fmaf(wv, v.z, acc.z); acc.w = fmaf(wv, v.w, acc.w);
    }
    *(float4*)&g_xdbl[(b*DBL + c)*LL + l0 + lg*4] = acc;
}

// ------------------------ K4: depthwise 1D conv(7, pad 3) + dt_proj + softplus
__global__ void k4_conv1d_delta(const float* __restrict__ xcw, const float* __restrict__ xcb,
                                const float* __restrict__ dpw, const float* __restrict__ dpb){
    __shared__ float xd[20][134];
    __shared__ float dtsm[4][128];
    __shared__ float bc[128][16];
    int tid = threadIdx.x;           // 128
    int b  = blockIdx.x >> 7;
    int l0 = (blockIdx.x & 127) << 7;
    for (int i = tid; i < 20*134; i += 128){
        int c = i / 134, o = i % 134;
        int gl = l0 + o - 3;
        xd[c][o] = (gl >= 0 && gl < LL) ? g_xdbl[(b*DBL + c)*LL + gl] : 0.f;
    }
    __syncthreads();
#pragma unroll
    for (int c = 0; c < 20; c++){
        float s = xcb[c];
#pragma unroll
        for (int j = 0; j < 7; j++) s = fmaf(xd[c][tid + j], xcw[c*7+j], s);
        if (c < 4) dtsm[c][tid] = s;
        else       bc[tid][c-4] = s;
    }
    __syncthreads();
    for (int i = tid; i < 1024; i += 128){
        g_Bn[(b*LL + l0)*NS + i] = bc[i >> 3][i & 7];
        g_Cn[(b*LL + l0)*NS + i] = bc[i >> 3][8 + (i & 7)];
    }
    float w0 = dpw[tid*4+0], w1 = dpw[tid*4+1], w2 = dpw[tid*4+2], w3 = dpw[tid*4+3];
    float bbias = dpb[tid];
    for (int l = 0; l < 128; l++){
        float s = bbias;
        s = fmaf(dtsm[0][l], w0, s);
        s = fmaf(dtsm[1][l], w1, s);
        s = fmaf(dtsm[2][l], w2, s);
        s = fmaf(dtsm[3][l], w3, s);
        g_delta[(b*LL + l0 + l)*DD + tid] = softplusf(s);
    }
}

// ------------------------------------------------ K5: scan phase 1 (chunk local)
__global__ void k5_scan1(const float* __restrict__ A_logs){
    __shared__ float Bs[CHL][NS];
    int tid = threadIdx.x;           // 128 (= d)
    int b  = blockIdx.x >> 7;
    int ch = blockIdx.x & 127;
    int l0 = ch << 7;
    for (int i = tid; i < CHL*NS; i += 128)
        ((float*)Bs)[i] = g_Bn[(b*LL + l0)*NS + i];
    float A[8];
#pragma unroll
    for (int n = 0; n < 8; n++)
        A[n] = -__expf(A_logs[tid*8+n]) * 1.4426950408889634f;  // pre-scaled for ex2
    float h[8], ap[8];
#pragma unroll
    for (int n = 0; n < 8; n++){ h[n] = 0.f; ap[n] = 1.f; }
    __syncthreads();
    for (int s = 0; s < CHL; s++){
        int gl = b*LL + l0 + s;
        float dl = g_delta[gl*DD + tid];
        float u  = g_xs[gl*DD + tid];
        float du = dl*u;
#pragma unroll
        for (int n = 0; n < 8; n++){
            float dA = ex2(dl*A[n]);
            ap[n] *= dA;
            h[n] = fmaf(dA, h[n], du*Bs[s][n]);
        }
    }
    int o = ((b*NCH + ch)*DD + tid)*NS;
#pragma unroll
    for (int n = 0; n < 8; n++){ g_ap[o+n] = ap[n]; g_hs[o+n] = h[n]; }
}

// ------------------------------------------------ K6: scan phase 2 (over chunks)
__global__ void k6_scan2(){
    int idx = blockIdx.x*256 + threadIdx.x;  // 4096 = B*D*NS
    int b  = idx >> 10;
    int dn = idx & 1023;
    float h = 0.f;
    for (int ch = 0; ch < NCH; ch++){
        int o = (b*NCH + ch)*DD*NS + dn;
        g_hi[o] = h;
        h = fmaf(g_ap[o], h, g_hs[o]);
    }
}

// ------------------------------------------- K7: scan phase 3 (replay + emit y)
__global__ void k7_scan3(const float* __restrict__ A_logs, const float* __restrict__ Dsv){
    __shared__ float Bs[CHL][NS];
    __shared__ float Cs[CHL][NS];
    int tid = threadIdx.x;           // 128 (= d)
    int b  = blockIdx.x >> 7;
    int ch = blockIdx.x & 127;
    int l0 = ch << 7;
    for (int i = tid; i < CHL*NS; i += 128){
        ((float*)Bs)[i] = g_Bn[(b*LL + l0)*NS + i];
        ((float*)Cs)[i] = g_Cn[(b*LL + l0)*NS + i];
    }
    float A[8];
#pragma unroll
    for (int n = 0; n < 8; n++)
        A[n] = -__expf(A_logs[tid*8+n]) * 1.4426950408889634f;
    float h[8];
    int o = ((b*NCH + ch)*DD + tid)*NS;
#pragma unroll
    for (int n = 0; n < 8; n++) h[n] = g_hi[o+n];
    float Dd = Dsv[tid];
    __syncthreads();
    for (int s = 0; s < CHL; s++){
        int gl = b*LL + l0 + s;
        float dl = g_delta[gl*DD + tid];
        float u  = g_xs[gl*DD + tid];
        float du = dl*u;
        float y = Dd * u;
#pragma unroll
        for (int n = 0; n < 8; n++){
            float dA = ex2(dl*A[n]);
            h[n] = fmaf(dA, h[n], du*Bs[s][n]);
            y = fmaf(h[n], Cs[s][n], y);
        }
        g_y[gl*DD + tid] = y;
    }
}

// ------------------------------------------- K8a: layernorm(d) * gelu(z) gate
__global__ void k8a_ln(const float* __restrict__ lg, const float* __restrict__ lb){
    int warp = threadIdx.x >> 5, lane = threadIdx.x & 31;
    int gl = blockIdx.x*8 + warp;    // [0, B*L)
    float4 v = *(const float4*)&g_y[gl*DD + lane*4];
    float s = v.x + v.y + v.z + v.w;
#pragma unroll
    for (int o = 16; o; o >>= 1) s += __shfl_xor_sync(0xffffffffu, s, o);
    float mu = s * 0.0078125f;
    float dx0 = v.x-mu, dx1 = v.y-mu, dx2 = v.z-mu, dx3 = v.w-mu;
    float q = dx0*dx0 + dx1*dx1 + dx2*dx2 + dx3*dx3;
#pragma unroll
    for (int o = 16; o; o >>= 1) q += __shfl_xor_sync(0xffffffffu, q, o);
    float rstd = rsqrtf(q*0.0078125f + 1e-5f);
    float4 g4 = *(const float4*)&lg[lane*4];
    float4 b4 = *(const float4*)&lb[lane*4];
    float4 z4 = *(const float4*)&g_zg[gl*DD + lane*4];
    float4 o4;
    o4.x = fmaf(dx0*rstd, g4.x, b4.x) * z4.x;
    o4.y = fmaf(dx1*rstd, g4.y, b4.y) * z4.y;
    o4.z = fmaf(dx2*rstd, g4.z, b4.z) * z4.z;
    o4.w = fmaf(dx3*rstd, g4.w, b4.w) * z4.w;
    *(float4*)&g_xin[gl*DD + lane*4] = o4;   // reuse g_xin as v
}

// ------------------------------------- K8b: out_proj GEMM + transpose to (b,c,l)
__global__ void k8b_outproj(const float* __restrict__ W2, float* __restrict__ out){
    __shared__ float vsm[32][132];   // [l][d], 528B rows (16B aligned)
    __shared__ float osm[64][33];
    int tid = threadIdx.x;           // 128
    int b  = blockIdx.x >> 9;
    int l0 = (blockIdx.x & 511) << 5;
    for (int i = tid; i < 4096; i += 128){
        int l = i >> 7, d = i & 127;
        vsm[l][d] = g_xin[(b*LL + l0 + l)*DD + d];
    }
    __syncthreads();
    int cg = (tid & 15) << 2;   // c tile base (4 rows)
    int lg = (tid >> 4) << 2;   // l tile base (4 cols)
    float acc[4][4];
#pragma unroll
    for (int j = 0; j < 4; j++)
#pragma unroll
        for (int i = 0; i < 4; i++) acc[j][i] = 0.f;
    for (int k = 0; k < 128; k += 4){
        float4 wv[4], vv[4];
#pragma unroll
        for (int j = 0; j < 4; j++) wv[j] = *(const float4*)&W2[(cg+j)*DD + k];
#pragma unroll
        for (int i = 0; i < 4; i++) vv[i] = *(const float4*)&vsm[lg+i][k];
#pragma unroll
        for (int j = 0; j < 4; j++)
#pragma unroll
            for (int i = 0; i < 4; i++){
                acc[j][i] = fmaf(wv[j].x, vv[i].x, acc[j][i]);
                acc[j][i] = fmaf(wv[j].y, vv[i].y, acc[j][i]);
                acc[j][i] = fmaf(wv[j].z, vv[i].z, acc[j][i]);
                acc[j][i] = fmaf(wv[j].w, vv[i].w, acc[j][i]);
            }
    }
#pragma unroll
    for (int j = 0; j < 4; j++)
#pragma unroll
        for (int i = 0; i < 4; i++) osm[cg+j][lg+i] = acc[j][i];
    __syncthreads();
    for (int i = tid; i < 2048; i += 128){
        int c = i >> 5, l = i & 31;
        out[(b*64 + c)*LL + l0 + l] = osm[c][l];
    }
}

extern "C" void kernel_launch(void* const* d_in, const int* in_sizes, int n_in,
                              void* d_out, int out_size){
    const float* x          = (const float*)d_in[0];
    const float* in_proj_w  = (const float*)d_in[1];
    const float* conv2d_w   = (const float*)d_in[2];
    const float* conv2d_b   = (const float*)d_in[3];
    const float* x_proj_w   = (const float*)d_in[4];
    const float* x_conv_w   = (const float*)d_in[5];
    const float* x_conv_b   = (const float*)d_in[6];
    const float* dt_proj_w  = (const float*)d_in[7];
    const float* dt_proj_b  = (const float*)d_in[8];
    const float* A_logs     = (const float*)d_in[9];
    const float* Ds         = (const float*)d_in[10];
    const float* ln_g       = (const float*)d_in[11];
    const float* ln_b       = (const float*)d_in[12];
    const float* out_proj_w = (const float*)d_in[13];
    float* out = (float*)d_out;

    k1_inproj      <<<2048, 256>>>(x, in_proj_w);
    k2_conv        <<<8192, 256>>>(conv2d_w, conv2d_b);
    k3_xproj       <<<2048, 160>>>(x_proj_w);
    k4_conv1d_delta<<< 512, 128>>>(x_conv_w, x_conv_b, dt_proj_w, dt_proj_b);
    k5_scan1       <<< 512, 128>>>(A_logs);
    k6_scan2       <<<  16, 256>>>();
    k7_scan3       <<< 512, 128>>>(A_logs, Ds);
    k8a_ln         <<<8192, 256>>>(ln_g, ln_b);
    k8b_outproj    <<<2048, 128>>>(out_proj_w, out);
}

// round 3
// speedup vs baseline: 1.6038x; 1.6038x over previous
#include <cuda_runtime.h>
#include <math.h>

#define BB 4
#define CIN 64
#define LL 16384
#define DD 128
#define DBL 20
#define NS 8
#define NCH 256
#define CHL 64

__device__ float g_xin [BB*LL*DD];   // (b,l,d) pre-conv xin
__device__ float g_zg  [BB*LL*DD];   // gelu(z), (b,l,d)
__device__ float g_xs  [BB*LL*DD];   // gelu(conv(xin)), (b,l,d)
__device__ float g_xdbl[BB*DBL*LL];  // (b,c,l) pre-1dconv
__device__ float g_delta[BB*LL*DD];  // (b,l,d)
__device__ float g_Bn  [BB*LL*NS];   // (b,l,n)
__device__ float g_Cn  [BB*LL*NS];   // (b,l,n)
__device__ float g_ap  [BB*NCH*DD*NS];
__device__ float g_hs  [BB*NCH*DD*NS];
__device__ float g_hi  [BB*NCH*DD*NS];
__device__ float g_y   [BB*LL*DD];   // (b,l,d)

__device__ __forceinline__ float gelu_exact(float x){
    return 0.5f*x*(1.f + erff(x*0.70710678118654752f));
}
__device__ __forceinline__ float ex2(float x){
    float r; asm("ex2.approx.f32 %0, %1;" : "=f"(r) : "f"(x)); return r;
}
__device__ __forceinline__ float softplus_fast(float x){
    float e = __expf(-fabsf(x));
    return fmaxf(x, 0.f) + __logf(1.f + e);
}

// ---------------------------------------------------------------- K1: in_proj
// out[b,l,d'] = sum_c x[b,c,l]*W[d',c]; d'<128 -> g_xin ; d'>=128 -> gelu -> g_zg
// grid = 1024 l-tiles * 4 d-tiles, block 128.  Tile: 64l x 64d, K=64.
__global__ void k1_inproj(const float* __restrict__ x, const float* __restrict__ Wp){
    __shared__ float xsm[64][68];   // [c][l]
    __shared__ float wsm[64][68];   // [c][d_local]
    int tid = threadIdx.x;
    int lt = blockIdx.x >> 2;
    int dt = blockIdx.x & 3;
    int b  = lt >> 8;
    int l0 = (lt & 255) << 6;
    int d0 = dt << 6;
    for (int i = tid; i < 1024; i += 128){
        int c = i >> 4, lq = i & 15;
        float4 v = *(const float4*)&x[(b*64 + c)*LL + l0 + lq*4];
        *(float4*)&xsm[c][lq*4] = v;
    }
    for (int i = tid; i < 1024; i += 128){
        int dl = i >> 4, c4 = i & 15;
        float4 v = *(const float4*)&Wp[(d0 + dl)*64 + c4*4];
        wsm[c4*4+0][dl] = v.x; wsm[c4*4+1][dl] = v.y;
        wsm[c4*4+2][dl] = v.z; wsm[c4*4+3][dl] = v.w;
    }
    __syncthreads();
    int tl = (tid & 15) << 2;
    int td = (tid >> 4) << 3;
    float acc[4][8];
#pragma unroll
    for (int i = 0; i < 4; i++)
#pragma unroll
        for (int j = 0; j < 8; j++) acc[i][j] = 0.f;
#pragma unroll 8
    for (int k = 0; k < 64; k++){
        float4 a  = *(const float4*)&xsm[k][tl];
        float4 b0 = *(const float4*)&wsm[k][td];
        float4 b1 = *(const float4*)&wsm[k][td+4];
        float av[4] = {a.x, a.y, a.z, a.w};
#pragma unroll
        for (int i = 0; i < 4; i++){
            acc[i][0] = fmaf(av[i], b0.x, acc[i][0]);
            acc[i][1] = fmaf(av[i], b0.y, acc[i][1]);
            acc[i][2] = fmaf(av[i], b0.z, acc[i][2]);
            acc[i][3] = fmaf(av[i], b0.w, acc[i][3]);
            acc[i][4] = fmaf(av[i], b1.x, acc[i][4]);
            acc[i][5] = fmaf(av[i], b1.y, acc[i][5]);
            acc[i][6] = fmaf(av[i], b1.z, acc[i][6]);
            acc[i][7] = fmaf(av[i], b1.w, acc[i][7]);
        }
    }
    bool isz = (d0 >= 128);
    int dbase = d0 - (isz ? 128 : 0) + td;
    float* dst0 = isz ? g_zg : g_xin;
#pragma unroll
    for (int li = 0; li < 4; li++){
        float* dst = dst0 + (b*LL + l0 + tl + li)*DD + dbase;
        float4 o0, o1;
        if (isz){
            o0.x = gelu_exact(acc[li][0]); o0.y = gelu_exact(acc[li][1]);
            o0.z = gelu_exact(acc[li][2]); o0.w = gelu_exact(acc[li][3]);
            o1.x = gelu_exact(acc[li][4]); o1.y = gelu_exact(acc[li][5]);
            o1.z = gelu_exact(acc[li][6]); o1.w = gelu_exact(acc[li][7]);
        } else {
            o0 = make_float4(acc[li][0], acc[li][1], acc[li][2], acc[li][3]);
            o1 = make_float4(acc[li][4], acc[li][5], acc[li][6], acc[li][7]);
        }
        *(float4*)&dst[0] = o0;
        *(float4*)&dst[4] = o1;
    }
}

// ------------------------------------------------- K2: depthwise 3x3 conv + gelu
// thread computes 4 consecutive w positions for 4 d channels. grid 2048, block 256.
__global__ void k2_conv(const float* __restrict__ cw, const float* __restrict__ cb){
    __shared__ float swf[1152];
    __shared__ float sbf[128];
    int tid = threadIdx.x;
    for (int i = tid; i < 1152; i += 256) swf[i] = cw[i];
    if (tid < 128) sbf[tid] = cb[tid];
    __syncthreads();
    int idx = blockIdx.x*256 + tid;
    int d4 = idx & 31;
    int p  = idx >> 5;
    int w0 = (p & 31) << 2;
    int h  = (p >> 5) & 127;
    int b  = p >> 12;
    int d  = d4 << 2;
    float wr[3][3][4];
#pragma unroll
    for (int dd = 0; dd < 4; dd++)
#pragma unroll
        for (int kh = 0; kh < 3; kh++)
#pragma unroll
            for (int kw = 0; kw < 3; kw++)
                wr[kh][kw][dd] = swf[(d+dd)*9 + kh*3 + kw];
    float4 a[4];
#pragma unroll
    for (int i = 0; i < 4; i++)
        a[i] = make_float4(sbf[d], sbf[d+1], sbf[d+2], sbf[d+3]);
#pragma unroll
    for (int kh = 0; kh < 3; kh++){
        int hh = h + kh - 1;
        if (hh < 0 || hh > 127) continue;
        const float* base = &g_xin[(b*LL + hh*128)*DD + d];
        float4 r[6];
#pragma unroll
        for (int j = 0; j < 6; j++){
            int wj = w0 - 1 + j;
            r[j] = (wj >= 0 && wj < 128) ? *(const float4*)&base[wj*DD]
                                         : make_float4(0.f,0.f,0.f,0.f);
        }
#pragma unroll
        for (int kw = 0; kw < 3; kw++){
#pragma unroll
            for (int i = 0; i < 4; i++){
                float4 v = r[i+kw];
                a[i].x = fmaf(v.x, wr[kh][kw][0], a[i].x);
                a[i].y = fmaf(v.y, wr[kh][kw][1], a[i].y);
                a[i].z = fmaf(v.z, wr[kh][kw][2], a[i].z);
                a[i].w = fmaf(v.w, wr[kh][kw][3], a[i].w);
            }
        }
    }
#pragma unroll
    for (int i = 0; i < 4; i++){
        float4 o;
        o.x = gelu_exact(a[i].x); o.y = gelu_exact(a[i].y);
        o.z = gelu_exact(a[i].z); o.w = gelu_exact(a[i].w);
        *(float4*)&g_xs[(b*LL + h*128 + w0 + i)*DD + d] = o;
    }
}

// ---------------------------------------------------------------- K3: x_proj
// g_xdbl[b,c,l] = sum_d g_xs[b,l,d] * xw[c,d].  grid 1024, block 128. tile 64l x 20c.
__global__ void k3_xproj(const float* __restrict__ xw){
    __shared__ float xsm[128][65];  // [k][l]
    __shared__ float wsm[128][21];  // [k][c]
    int tid = threadIdx.x;
    int b  = blockIdx.x >> 8;
    int l0 = (blockIdx.x & 255) << 6;
    for (int i = tid; i < 2048; i += 128){  // 64 rows * 32 float4
        int l = i >> 5, dq = i & 31;
        float4 v = *(const float4*)&g_xs[(b*LL + l0 + l)*DD + dq*4];
        xsm[dq*4+0][l] = v.x; xsm[dq*4+1][l] = v.y;
        xsm[dq*4+2][l] = v.z; xsm[dq*4+3][l] = v.w;
    }
    for (int i = tid; i < 2560; i += 128){
        int c = i >> 7, k = i & 127;
        wsm[k][c] = xw[i];
    }
    __syncthreads();
    int lq = tid & 63;
    int c0 = (tid >> 6) * 10;
    float acc[10];
#pragma unroll
    for (int j = 0; j < 10; j++) acc[j] = 0.f;
#pragma unroll 4
    for (int k = 0; k < 128; k++){
        float xv = xsm[k][lq];
#pragma unroll
        for (int j = 0; j < 10; j++)
            acc[j] = fmaf(xv, wsm[k][c0+j], acc[j]);
    }
    __syncthreads();
    float* osm = (float*)xsm;   // reuse as [20][68]
#pragma unroll
    for (int j = 0; j < 10; j++) osm[(c0+j)*68 + lq] = acc[j];
    __syncthreads();
    for (int i = tid; i < 320; i += 128){   // 20c * 16 float4
        int c = i >> 4, q = i & 15;
        float4 v = *(const float4*)&osm[c*68 + q*4];
        *(float4*)&g_xdbl[(b*DBL + c)*LL + l0 + q*4] = v;
    }
}

// ------------------------ K4: depthwise 1D conv(7, pad 3) + dt_proj + softplus
// grid 1024 (64 l each), block 128.
__global__ void k4_conv1d_delta(const float* __restrict__ xcw, const float* __restrict__ xcb,
                                const float* __restrict__ dpw, const float* __restrict__ dpb){
    __shared__ float xd[20][72];
    __shared__ float dtsm[4][64];
    __shared__ float bcs[64][17];
    int tid = threadIdx.x;
    int b  = blockIdx.x >> 8;
    int l0 = (blockIdx.x & 255) << 6;
    for (int i = tid; i < 1400; i += 128){
        int c = i / 70, o = i % 70;
        int gl = l0 + o - 3;
        xd[c][o] = (gl >= 0 && gl < LL) ? g_xdbl[(b*DBL + c)*LL + gl] : 0.f;
    }
    __syncthreads();
    for (int i = tid; i < 1280; i += 128){
        int c = i >> 6, l = i & 63;
        float s = xcb[c];
#pragma unroll
        for (int j = 0; j < 7; j++) s = fmaf(xd[c][l + j], xcw[c*7+j], s);
        if (c < 4) dtsm[c][l] = s;
        else       bcs[l][c-4] = s;
    }
    __syncthreads();
    for (int i = tid; i < 512; i += 128){
        int l = i >> 3, n = i & 7;
        g_Bn[(b*LL + l0 + l)*NS + n] = bcs[l][n];
        g_Cn[(b*LL + l0 + l)*NS + n] = bcs[l][8+n];
    }
    float w0 = dpw[tid*4+0], w1 = dpw[tid*4+1], w2 = dpw[tid*4+2], w3 = dpw[tid*4+3];
    float bias = dpb[tid];
#pragma unroll 4
    for (int l = 0; l < 64; l++){
        float s = bias;
        s = fmaf(dtsm[0][l], w0, s);
        s = fmaf(dtsm[1][l], w1, s);
        s = fmaf(dtsm[2][l], w2, s);
        s = fmaf(dtsm[3][l], w3, s);
        g_delta[(b*LL + l0 + l)*DD + tid] = softplus_fast(s);
    }
}

// ------------------------------------------------ K5: scan phase 1 (chunk local)
__global__ void k5_scan1(const float* __restrict__ A_logs){
    __shared__ float Bs[CHL][NS];
    int tid = threadIdx.x;
    int b  = blockIdx.x >> 8;
    int ch = blockIdx.x & 255;
    int l0 = ch << 6;
    for (int i = tid; i < CHL*NS; i += 128)
        ((float*)Bs)[i] = g_Bn[(b*LL + l0)*NS + i];
    float A[8];
#pragma unroll
    for (int n = 0; n < 8; n++)
        A[n] = -__expf(A_logs[tid*8+n]) * 1.4426950408889634f;
    float h[8], ap[8];
#pragma unroll
    for (int n = 0; n < 8; n++){ h[n] = 0.f; ap[n] = 1.f; }
    __syncthreads();
    int base = (b*LL + l0)*DD + tid;
    float dl = g_delta[base], u = g_xs[base];
#pragma unroll 2
    for (int s = 0; s < CHL; s++){
        float dn = 0.f, un = 0.f;
        if (s < CHL-1){ dn = g_delta[base + (s+1)*DD]; un = g_xs[base + (s+1)*DD]; }
        float du = dl*u;
#pragma unroll
        for (int n = 0; n < 8; n++){
            float dA = ex2(dl*A[n]);
            ap[n] *= dA;
            h[n] = fmaf(dA, h[n], du*Bs[s][n]);
        }
        dl = dn; u = un;
    }
    int o = ((b*NCH + ch)*DD + tid)*NS;
#pragma unroll
    for (int n = 0; n < 8; n++){ g_ap[o+n] = ap[n]; g_hs[o+n] = h[n]; }
}

// ------------------------------------------------ K6: scan phase 2 (over chunks)
__global__ void k6_scan2(){
    int idx = blockIdx.x*256 + threadIdx.x;  // 4096 = B*D*NS
    int b  = idx >> 10;
    int dn = idx & 1023;
    const float* ap = g_ap + b*NCH*1024 + dn;
    const float* hs = g_hs + b*NCH*1024 + dn;
    float*       hi = g_hi + b*NCH*1024 + dn;
    float h = 0.f;
#pragma unroll 8
    for (int ch = 0; ch < NCH; ch++){
        int o = ch << 10;
        float a = ap[o], s = hs[o];
        hi[o] = h;
        h = fmaf(a, h, s);
    }
}

// ------------------------------------------- K7: scan phase 3 (replay + emit y)
__global__ void k7_scan3(const float* __restrict__ A_logs, const float* __restrict__ Dsv){
    __shared__ float Bs[CHL][NS];
    __shared__ float Cs[CHL][NS];
    int tid = threadIdx.x;
    int b  = blockIdx.x >> 8;
    int ch = blockIdx.x & 255;
    int l0 = ch << 6;
    for (int i = tid; i < CHL*NS; i += 128){
        ((float*)Bs)[i] = g_Bn[(b*LL + l0)*NS + i];
        ((float*)Cs)[i] = g_Cn[(b*LL + l0)*NS + i];
    }
    float A[8];
#pragma unroll
    for (int n = 0; n < 8; n++)
        A[n] = -__expf(A_logs[tid*8+n]) * 1.4426950408889634f;
    float h[8];
    int o = ((b*NCH + ch)*DD + tid)*NS;
#pragma unroll
    for (int n = 0; n < 8; n++) h[n] = g_hi[o+n];
    float Dd = Dsv[tid];
    __syncthreads();
    int base = (b*LL + l0)*DD + tid;
    float dl = g_delta[base], u = g_xs[base];
#pragma unroll 2
    for (int s = 0; s < CHL; s++){
        float dn = 0.f, un = 0.f;
        if (s < CHL-1){ dn = g_delta[base + (s+1)*DD]; un = g_xs[base + (s+1)*DD]; }
        float du = dl*u;
        float y = Dd * u;
#pragma unroll
        for (int n = 0; n < 8; n++){
            float dA = ex2(dl*A[n]);
            h[n] = fmaf(dA, h[n], du*Bs[s][n]);
            y = fmaf(h[n], Cs[s][n], y);
        }
        g_y[base + s*DD] = y;
        dl = dn; u = un;
    }
}

// --------------- K8: fused LayerNorm * gate + out_proj GEMM + transpose
// g_zg already holds gelu(z) from k1 — multiply directly, NO second gelu.
// grid 1024 (64 l-tile), block 128. GEMM 64l x 64c, K=128 in two 64-k halves.
__global__ void k8_fused(const float* __restrict__ lg, const float* __restrict__ lb,
                         const float* __restrict__ W2, float* __restrict__ out){
    __shared__ float vsm[64][68];   // [k_local][l]
    __shared__ float wsm[64][68];   // [k_local][c]
    int tid = threadIdx.x;
    int b  = blockIdx.x >> 8;
    int l0 = (blockIdx.x & 255) << 6;
    int r = tid >> 1;        // row (l) 0..63
    int q = tid & 1;         // k-half owned by this thread
    const float* yrow = &g_y[(b*LL + l0 + r)*DD + q*64];
    const float* zrow = &g_zg[(b*LL + l0 + r)*DD + q*64];
    float s = 0.f, ss = 0.f;
#pragma unroll
    for (int i = 0; i < 16; i++){
        float4 v = *(const float4*)&yrow[i*4];
        s  += v.x + v.y + v.z + v.w;
        ss += v.x*v.x + v.y*v.y + v.z*v.z + v.w*v.w;
    }
    s  += __shfl_xor_sync(0xffffffffu, s, 1);
    ss += __shfl_xor_sync(0xffffffffu, ss, 1);
    float mu  = s * 0.0078125f;
    float var = fmaxf(ss * 0.0078125f - mu*mu, 0.f);
    float rstd = rsqrtf(var + 1e-5f);

    int tc = tid & 15;       // c group: c = tc*4
    int tl = tid >> 4;       // l group: l = tl*8
    float acc[8][4];
#pragma unroll
    for (int i = 0; i < 8; i++)
#pragma unroll
        for (int j = 0; j < 4; j++) acc[i][j] = 0.f;

    for (int half = 0; half < 2; half++){
        __syncthreads();
        if (q == half){
            // this thread's 64 k-values are exactly this half: compute v, store vsm
#pragma unroll 4
            for (int i = 0; i < 16; i++){
                float4 yv = *(const float4*)&yrow[i*4];
                float4 zv = *(const float4*)&zrow[i*4];   // already gelu(z)
                float4 gv = *(const float4*)&lg[q*64 + i*4];
                float4 bv = *(const float4*)&lb[q*64 + i*4];
                vsm[i*4+0][r] = fmaf((yv.x-mu)*rstd, gv.x, bv.x) * zv.x;
                vsm[i*4+1][r] = fmaf((yv.y-mu)*rstd, gv.y, bv.y) * zv.y;
                vsm[i*4+2][r] = fmaf((yv.z-mu)*rstd, gv.z, bv.z) * zv.z;
                vsm[i*4+3][r] = fmaf((yv.w-mu)*rstd, gv.w, bv.w) * zv.w;
            }
        } else {
            // other 64 threads load W half: wsm[k][c] from W2[c*128 + half*64 + k]
            for (int i = r; i < 1024; i += 64){
                int c = i >> 4, kq = i & 15;
                float4 wv = *(const float4*)&W2[c*DD + half*64 + kq*4];
                wsm[kq*4+0][c] = wv.x; wsm[kq*4+1][c] = wv.y;
                wsm[kq*4+2][c] = wv.z; wsm[kq*4+3][c] = wv.w;
            }
        }
        __syncthreads();
#pragma unroll 4
        for (int k = 0; k < 64; k++){
            float4 w  = *(const float4*)&wsm[k][tc*4];
            float4 v0 = *(const float4*)&vsm[k][tl*8];
            float4 v1 = *(const float4*)&vsm[k][tl*8+4];
            float vv[8] = {v0.x, v0.y, v0.z, v0.w, v1.x, v1.y, v1.z, v1.w};
#pragma unroll
            for (int i = 0; i < 8; i++){
                acc[i][0] = fmaf(vv[i], w.x, acc[i][0]);
                acc[i][1] = fmaf(vv[i], w.y, acc[i][1]);
                acc[i][2] = fmaf(vv[i], w.z, acc[i][2]);
                acc[i][3] = fmaf(vv[i], w.w, acc[i][3]);
            }
        }
    }
    __syncthreads();
    // stage result into vsm as osm[c][l]
#pragma unroll
    for (int i = 0; i < 8; i++)
#pragma unroll
        for (int j = 0; j < 4; j++)
            vsm[tc*4+j][tl*8+i] = acc[i][j];
    __syncthreads();
    for (int i = tid; i < 1024; i += 128){
        int c = i >> 4, lq = i & 15;
        float4 v = *(const float4*)&vsm[c][lq*4];
        *(float4*)&out[(b*64 + c)*LL + l0 + lq*4] = v;
    }
}

extern "C" void kernel_launch(void* const* d_in, const int* in_sizes, int n_in,
                              void* d_out, int out_size){
    const float* x          = (const float*)d_in[0];
    const float* in_proj_w  = (const float*)d_in[1];
    const float* conv2d_w   = (const float*)d_in[2];
    const float* conv2d_b   = (const float*)d_in[3];
    const float* x_proj_w   = (const float*)d_in[4];
    const float* x_conv_w   = (const float*)d_in[5];
    const float* x_conv_b   = (const float*)d_in[6];
    const float* dt_proj_w  = (const float*)d_in[7];
    const float* dt_proj_b  = (const float*)d_in[8];
    const float* A_logs     = (const float*)d_in[9];
    const float* Ds         = (const float*)d_in[10];
    const float* ln_g       = (const float*)d_in[11];
    const float* ln_b       = (const float*)d_in[12];
    const float* out_proj_w = (const float*)d_in[13];
    float* out = (float*)d_out;

    k1_inproj      <<<4096, 128>>>(x, in_proj_w);
    k2_conv        <<<2048, 256>>>(conv2d_w, conv2d_b);
    k3_xproj       <<<1024, 128>>>(x_proj_w);
    k4_conv1d_delta<<<1024, 128>>>(x_conv_w, x_conv_b, dt_proj_w, dt_proj_b);
    k5_scan1       <<<1024, 128>>>(A_logs);
    k6_scan2       <<<  16, 256>>>();
    k7_scan3       <<<1024, 128>>>(A_logs, Ds);
    k8_fused       <<<1024, 128>>>(ln_g, ln_b, out_proj_w, out);
}